// round 11
// baseline (speedup 1.0000x reference)
#include <cuda_runtime.h>
#include <math.h>

// Problem constants (N=128 images, P=16 control points, S=128 grid)
#define NIMG 128
#define NP   16
#define NSEG (NP-1)            // 15 segments
#define SDIM 128
#define RAD  4                 // 9-tap Gaussian: dropped taps <= 1.1e-7 (safe vs 1e-3 tol)
#define KW   (2*RAD+1)

#define BT     256             // threads per CTA
#define SLICES 4               // CTAs per image
#define SR     32              // output rows per CTA
#define LR     (SR + 2*RAD)    // 40 histogram rows per slice (with halo)
#define HP     132             // hist y pitch (y in 0..128), mult of 4
#define M1P    137             // m1 pitch; 137%32=9 coprime -> conflict-free column walks
#define B_SMEM_F (LR*HP + SR*M1P)   // 5280 + 4384 = 9664 floats (~38.7 KB)

// Compile-time taps exp(-d^2), d = idx-RAD  -> FFMA immediates
__device__ __constant__ const float Wc[KW] = {
    1.1253517471925912e-7f, 1.2340980408667956e-4f, 0.018315638888734179f,
    0.36787944117144233f, 1.0f, 0.36787944117144233f,
    0.018315638888734179f, 1.2340980408667956e-4f, 1.1253517471925912e-7f
};

__global__ __launch_bounds__(BT)
void plotline2_kernel(const float* __restrict__ points, float* __restrict__ out)
{
    extern __shared__ float sm[];
    float* hs = sm;                  // [LR][HP] slice histogram
    float* m1 = sm + LR * HP;        // [SR][M1P]

    const int n   = blockIdx.x >> 2;
    const int q   = blockIdx.x & 3;
    const int s0  = q * SR;
    const int tid = threadIdx.x;

    // ---- zero hist slab + m1 halo columns ----
    {
        float4 z = make_float4(0.f, 0.f, 0.f, 0.f);
        float4* h4 = (float4*)hs;
        for (int i = tid; i < (LR * HP) / 4; i += BT) h4[i] = z;
        for (int i = tid; i < SR * 2 * RAD; i += BT) {
            int r = i / (2 * RAD);
            int c = i - r * (2 * RAD);
            int col = (c < RAD) ? c : (M1P - 2 * RAD + c);   // 0..3 or 133..136
            m1[r * M1P + col] = 0.0f;
        }
    }
    __syncthreads();

    // ---- stage 1: interpolate 1920 points, histogram those in our x-window ----
    // Permuted mapping: seg = idx % 15, i = idx / 15 — the 32 lanes of a warp
    // hit 15 different segments -> spread-address smem atomics (no same-pixel
    // serialization from consecutive interpolation steps).
    const float inv = 1.0f / (float)SDIM;
    const float* pn = points + n * NP * 2;
    const int lrbase = s0 - RAD;
    for (int idx = tid; idx < NSEG * SDIM; idx += BT) {
        int i   = idx / NSEG;              // 0..127 (step)
        int seg = idx - i * NSEG;          // 0..14  (segment)
        float t   = (float)i * inv;
        float omt = 1.0f - t;
        float x0 = pn[seg * 2 + 0];
        float x1 = pn[seg * 2 + 2];
        // match XLA: mul, mul, add — no fma contraction
        float x = __fadd_rn(__fmul_rn(omt, x0), __fmul_rn(t, x1));
        int ix = (int)rintf(x);            // round-half-to-even, 0..128
        int lr = ix - lrbase;              // local hist row
        if ((unsigned)lr < (unsigned)LR) { // early-out before y work (~69% skip)
            float y0 = pn[seg * 2 + 1];
            float y1 = pn[seg * 2 + 3];
            float y = __fadd_rn(__fmul_rn(omt, y0), __fmul_rn(t, y1));
            int iy = (int)rintf(y);
            atomicAdd(&hs[lr * HP + iy], 1.0f);
        }
    }
    __syncthreads();

    // ---- stage 2: conv along x: m1[s][y+RAD] = sum_d W[d]*hs[s+d][y] ----
    // lanes -> consecutive y (stride 1, conflict-free)
    for (int item = tid; item < 4 * 129; item += BT) {
        int sg = item / 129;
        int y  = item - sg * 129;          // 0..128
        int sbase = sg * 8;
        float v[8 + KW - 1];               // 16
#pragma unroll
        for (int j = 0; j < 8 + KW - 1; ++j)
            v[j] = hs[(sbase + j) * HP + y];
#pragma unroll
        for (int i = 0; i < 8; ++i) {
            float acc = 0.0f;
#pragma unroll
            for (int d = 0; d < KW; ++d)
                acc = fmaf(Wc[d], v[i + d], acc);
            m1[(sbase + i) * M1P + (y + RAD)] = acc;
        }
    }
    __syncthreads();

    // ---- stage 3: conv along y + tanh -> direct gmem store ----
    // lanes -> consecutive s (m1 bank stride 9, conflict-free); each thread
    // emits 8 contiguous t-values = one exact 32B sector (2x STG.128).
    float* outn = out + ((size_t)n * SDIM + s0) * SDIM;
    for (int item = tid; item < SR * 16; item += BT) {
        int s  = item & 31;
        int tb = (item >> 5) * 8;
        float v[8 + KW - 1];
#pragma unroll
        for (int j = 0; j < 8 + KW - 1; ++j)
            v[j] = m1[s * M1P + tb + j];
        float r[8];
#pragma unroll
        for (int i = 0; i < 8; ++i) {
            float acc = 0.0f;
#pragma unroll
            for (int d = 0; d < KW; ++d)
                acc = fmaf(Wc[d], v[i + d], acc);
            // tanh(x), x >= 0:  1 - 2/(e^{2x}+1); inf-safe
            float e = __expf(2.0f * acc);
            r[i] = 1.0f - __fdividef(2.0f, e + 1.0f);
        }
        float4* dst = (float4*)(outn + s * SDIM + tb);
        dst[0] = make_float4(r[0], r[1], r[2], r[3]);
        dst[1] = make_float4(r[4], r[5], r[6], r[7]);
    }
}

extern "C" void kernel_launch(void* const* d_in, const int* in_sizes, int n_in,
                              void* d_out, int out_size)
{
    const float* points = (const float*)d_in[0];
    float* out = (float*)d_out;

    size_t smem = B_SMEM_F * sizeof(float);   // ~38.7 KB
    cudaFuncSetAttribute(plotline2_kernel,
                         cudaFuncAttributeMaxDynamicSharedMemorySize, (int)smem);
    plotline2_kernel<<<NIMG * SLICES, BT, smem>>>(points, out);
}

// round 12
// speedup vs baseline: 1.0201x; 1.0201x over previous
#include <cuda_runtime.h>
#include <math.h>

// Problem constants (N=128 images, P=16 control points, S=128 grid)
#define NIMG 128
#define NP   16
#define NSEG (NP-1)            // 15 segments
#define SDIM 128
#define RAD  4                 // 9-tap Gaussian: dropped taps <= 1.1e-7 (safe vs 1e-3 tol)
#define KW   (2*RAD+1)

#define BT     256             // threads per CTA
#define SLICES 4               // CTAs per image
#define SR     32              // output rows per CTA
#define LR     (SR + 2*RAD)    // 40 histogram rows per slice (with halo)
#define HP     132             // hist y pitch (y in 0..128), even, mult of 4
#define M1TP   36              // m1T pitch (rows 16B-aligned: 36%4==0)
#define M1TR   136             // m1T rows: t' = 0..135 (t' = y + RAD, y in -4..131)
#define RESP   132             // res staging pitch (rows 16B-aligned)
#define SMEM_F (LR*HP + M1TR*M1TP)   // 5280 + 4896 = 10176 floats (~40.7 KB)

typedef unsigned long long u64;

// ---- packed f32x2 helpers (PTX-only; ptxas never auto-fuses) ----
__device__ __forceinline__ u64 pack2(float lo, float hi) {
    u64 r; asm("mov.b64 %0,{%1,%2};" : "=l"(r) : "f"(lo), "f"(hi)); return r;
}
__device__ __forceinline__ void unpack2(u64 v, float& lo, float& hi) {
    asm("mov.b64 {%0,%1},%2;" : "=f"(lo), "=f"(hi) : "l"(v));
}
__device__ __forceinline__ u64 fma2(u64 a, u64 b, u64 c) {
    u64 d; asm("fma.rn.f32x2 %0,%1,%2,%3;" : "=l"(d) : "l"(a), "l"(b), "l"(c)); return d;
}

// tanh(x) for x>=0; for x<=0.01, tanh(x)=x within 3.3e-7 abs
__device__ __forceinline__ float tanh_pos(float x) {
    if (x > 0.01f) {
        float e = __expf(x + x);                  // inf-safe: e=inf -> result 1
        x = 1.0f - __fdividef(2.0f, e + 1.0f);
    }
    return x;
}

__global__ __launch_bounds__(BT, 4)
void plotline2_kernel(const float* __restrict__ points, float* __restrict__ out)
{
    extern __shared__ float sm[];
    float* hs  = sm;                 // [LR][HP] slice histogram; later reused as res[SR][RESP]
    float* m1t = sm + LR * HP;       // [M1TR][M1TP], m1T[t'][s]

    const int n   = blockIdx.x >> 2;
    const int q   = blockIdx.x & 3;
    const int s0  = q * SR;
    const int tid = threadIdx.x;

    // Compile-time taps exp(-d^2) -> immediates
    constexpr float Ws[KW] = {
        1.1253517471925912e-7f, 1.2340980408667956e-4f, 0.018315638888734179f,
        0.36787944117144233f, 1.0f, 0.36787944117144233f,
        0.018315638888734179f, 1.2340980408667956e-4f, 1.1253517471925912e-7f
    };

    // ---- zero hist slab + m1T halo rows (0..3, 134..135; stage 2 writes rows 4..133) ----
    {
        float4 z = make_float4(0.f, 0.f, 0.f, 0.f);
        float4* h4 = (float4*)hs;
        for (int i = tid; i < (LR * HP) / 4; i += BT) h4[i] = z;
        for (int i = tid; i < 6 * M1TP; i += BT) {
            int r = i / M1TP;
            int c = i - r * M1TP;
            int row = (r < 4) ? r : (M1TR - 6 + r);     // 0..3 or 134..135
            m1t[row * M1TP + c] = 0.0f;
        }
    }
    __syncthreads();

    // ---- stage 1: interpolate 1920 points, histogram those in our x-window ----
    // Permuted mapping (seg = idx%15) -> warp lanes spread over 15 segments
    // => spread-address smem atomics.
    const float inv = 1.0f / (float)SDIM;
    const float* pn = points + n * NP * 2;
    const int lrbase = s0 - RAD;
    for (int idx = tid; idx < NSEG * SDIM; idx += BT) {
        int i   = idx / NSEG;              // 0..127 (step)
        int seg = idx - i * NSEG;          // 0..14  (segment)
        float t   = (float)i * inv;
        float omt = 1.0f - t;
        float x0 = pn[seg * 2 + 0];
        float x1 = pn[seg * 2 + 2];
        // match XLA: mul, mul, add — no fma contraction
        float x = __fadd_rn(__fmul_rn(omt, x0), __fmul_rn(t, x1));
        int ix = (int)rintf(x);            // round-half-to-even, 0..128
        int lr = ix - lrbase;
        if ((unsigned)lr < (unsigned)LR) {
            float y0 = pn[seg * 2 + 1];
            float y1 = pn[seg * 2 + 3];
            float y = __fadd_rn(__fmul_rn(omt, y0), __fmul_rn(t, y1));
            int iy = (int)rintf(y);
            atomicAdd(&hs[lr * HP + iy], 1.0f);
        }
    }
    __syncthreads();

    // ---- stage 2: conv over x, packed over a y-pair; writes m1T transposed ----
    // item = (sg, yp): outputs s = sg*8..sg*8+7 for y = 2yp, 2yp+1.
    // LDS.64 hs[row][2yp..2yp+1] is directly a packed operand.
    {
        u64 Wp[KW];
#pragma unroll
        for (int d = 0; d < KW; ++d) Wp[d] = pack2(Ws[d], Ws[d]);

        for (int item = tid; item < 4 * 65; item += BT) {      // 260 items
            int sg = item / 65;
            int yp = item - sg * 65;       // 0..64 -> y = 0..128 (+pad y=129 reads zero col)
            int y  = 2 * yp;
            int sbase = sg * 8;
            u64 acc[8];
#pragma unroll
            for (int i = 0; i < 8; ++i) acc[i] = 0ull;
#pragma unroll
            for (int j = 0; j < 8 + KW - 1; ++j) {             // 16 rows
                u64 v = *(const u64*)&hs[(sbase + j) * HP + y];
#pragma unroll
                for (int i = 0; i < 8; ++i) {
                    int d = j - i;
                    if (d >= 0 && d < KW) acc[i] = fma2(Wp[d], v, acc[i]);
                }
            }
            // unpack -> two m1T rows (t' = y+RAD, y+RAD+1), cols sbase..sbase+7
            float r0[8], r1[8];
#pragma unroll
            for (int i = 0; i < 8; ++i) unpack2(acc[i], r0[i], r1[i]);
            float4* p0 = (float4*)&m1t[(y + RAD)     * M1TP + sbase];
            float4* p1 = (float4*)&m1t[(y + RAD + 1) * M1TP + sbase];
            p0[0] = make_float4(r0[0], r0[1], r0[2], r0[3]);
            p0[1] = make_float4(r0[4], r0[5], r0[6], r0[7]);
            p1[0] = make_float4(r1[0], r1[1], r1[2], r1[3]);
            p1[1] = make_float4(r1[4], r1[5], r1[6], r1[7]);
        }
    }
    __syncthreads();

    // ---- stage 3: conv over t, packed over an s-pair; tanh; stage into res ----
    // item: sp = tid&15 (s-pair 2sp,2sp+1), tg = tid>>4 (t-base tg*8). 256 items.
    float* res = hs;                       // [SR][RESP] (4224 <= 5280 floats)
    {
        u64 Wp[KW];
#pragma unroll
        for (int d = 0; d < KW; ++d) Wp[d] = pack2(Ws[d], Ws[d]);

        int sp = tid & 15;
        int tb = (tid >> 4) * 8;
        u64 acc[8];
#pragma unroll
        for (int i = 0; i < 8; ++i) acc[i] = 0ull;
#pragma unroll
        for (int j = 0; j < 8 + KW - 1; ++j) {                 // 16 m1T rows
            u64 v = *(const u64*)&m1t[(tb + j) * M1TP + 2 * sp];
#pragma unroll
            for (int i = 0; i < 8; ++i) {
                int d = j - i;
                if (d >= 0 && d < KW) acc[i] = fma2(Wp[d], v, acc[i]);
            }
        }
        float r0[8], r1[8];
#pragma unroll
        for (int i = 0; i < 8; ++i) {
            unpack2(acc[i], r0[i], r1[i]);
            r0[i] = tanh_pos(r0[i]);
            r1[i] = tanh_pos(r1[i]);
        }
        float4* p0 = (float4*)&res[(2 * sp)     * RESP + tb];
        float4* p1 = (float4*)&res[(2 * sp + 1) * RESP + tb];
        p0[0] = make_float4(r0[0], r0[1], r0[2], r0[3]);
        p0[1] = make_float4(r0[4], r0[5], r0[6], r0[7]);
        p1[0] = make_float4(r1[0], r1[1], r1[2], r1[3]);
        p1[1] = make_float4(r1[4], r1[5], r1[6], r1[7]);
    }
    __syncthreads();

    // ---- stage 4: coalesced copy res -> out[n][s0..s0+31][*] ----
    {
        float4* dst = (float4*)(out + ((size_t)n * SDIM + s0) * SDIM);
        for (int i = tid; i < SR * (SDIM / 4); i += BT) {
            int s = i >> 5;
            int c = (i & 31) * 4;
            const float4* src = (const float4*)&res[s * RESP + c];
            dst[i] = *src;
        }
    }
}

extern "C" void kernel_launch(void* const* d_in, const int* in_sizes, int n_in,
                              void* d_out, int out_size)
{
    const float* points = (const float*)d_in[0];
    float* out = (float*)d_out;

    size_t smem = SMEM_F * sizeof(float);   // ~40.7 KB
    cudaFuncSetAttribute(plotline2_kernel,
                         cudaFuncAttributeMaxDynamicSharedMemorySize, (int)smem);
    plotline2_kernel<<<NIMG * SLICES, BT, smem>>>(points, out);
}